// round 11
// baseline (speedup 1.0000x reference)
#include <cuda_runtime.h>
#include <cuda_bf16.h>
#include <cstdint>

#define Bv 4
#define Sv 2048
#define Dv 2048
#define Hv 16
#define DHv 128
#define WINv 128
#define Mv 64
#define Cv 256
#define FFv 8192
#define nWv 16

#define BSv (Bv*Sv)
#define BSDv ((size_t)Bv*Sv*Dv)
#define B3SDv (3*BSDv)
#define BMDv ((size_t)Bv*Mv*Dv)
#define BSFFv ((size_t)Bv*Sv*FFv)
#define BDv (Bv*Dv)
#define BCv (Bv*Cv)
#define D2 ((size_t)2048*2048)

// fp32 scratch
__device__ float d_qkv[B3SDv];
__device__ float d_lcp[BSDv];
__device__ float d_h2[BSDv];
__device__ float d_qg[BSDv];
__device__ float d_kg[BMDv];
__device__ float d_vg[BMDv];
__device__ float d_gatelin[BSDv];
__device__ float d_go[BSDv];
__device__ float d_gmg[BSDv];
__device__ float d_qm[BMDv];
__device__ float d_km[BSDv];
__device__ float d_vm[BSDv];
__device__ float d_pooled[BDv];
__device__ float d_zlin[BCv];
__device__ float d_gclin[BCv];
__device__ float d_ns[BCv];
__device__ float d_sp[BDv];
__device__ float d_spf[BDv];
__device__ float d_fused[BSDv];
__device__ float d_hbuf[BSDv];
__device__ float d_ffa[BSFFv];

// bf16 weight arena (transposed [N][K]) hi/lo
#define OFF_QKV  ((size_t)0)
#define OFF_LO   ((size_t)12582912)
#define OFF_GQ   (OFF_LO   + D2)
#define OFF_GK   (OFF_GQ   + D2)
#define OFF_GV   (OFF_GK   + D2)
#define OFF_GO   (OFF_GV   + D2)
#define OFF_GATE (OFF_GO   + D2)
#define OFF_MQ   (OFF_GATE + D2)
#define OFF_MK   (OFF_MQ   + D2)
#define OFF_MV   (OFF_MK   + D2)
#define OFF_MO   (OFF_MV   + D2)
#define OFF_F1   (OFF_MO   + D2)
#define OFF_F2   (OFF_F1   + D2)
#define OFF_FF1  (OFF_F2   + D2)
#define OFF_FF2  (OFF_FF1  + (size_t)16777216)
#define W_TOTAL  (OFF_FF2  + (size_t)16777216)
__device__ __nv_bfloat16 warena_h[W_TOTAL];
__device__ __nv_bfloat16 warena_l[W_TOTAL];
__device__ __nv_bfloat16 act_h[BSFFv];
__device__ __nv_bfloat16 act_l[BSFFv];
__device__ __nv_bfloat16 act2_h[BMDv];
__device__ __nv_bfloat16 act2_l[BMDv];

__device__ __forceinline__ uint32_t smem_u32(const void* p) {
    uint32_t a;
    asm("{ .reg .u64 t; cvta.to.shared.u64 t, %1; cvt.u32.u64 %0, t; }" : "=r"(a) : "l"(p));
    return a;
}
__device__ __forceinline__ void cpa16(uint32_t dst, const void* src) {
    asm volatile("cp.async.cg.shared.global [%0], [%1], 16;" :: "r"(dst), "l"(src) : "memory");
}
__device__ __forceinline__ void ldm4(uint32_t* r, uint32_t addr) {
    asm volatile("ldmatrix.sync.aligned.m8n8.x4.shared.b16 {%0,%1,%2,%3}, [%4];"
        : "=r"(r[0]), "=r"(r[1]), "=r"(r[2]), "=r"(r[3]) : "r"(addr));
}
__device__ __forceinline__ void mma16816(float* c, const uint32_t* a, const uint32_t* b) {
    asm volatile(
        "mma.sync.aligned.m16n8k16.row.col.f32.bf16.bf16.f32 "
        "{%0,%1,%2,%3}, {%4,%5,%6,%7}, {%8,%9}, {%0,%1,%2,%3};"
        : "+f"(c[0]), "+f"(c[1]), "+f"(c[2]), "+f"(c[3])
        : "r"(a[0]), "r"(a[1]), "r"(a[2]), "r"(a[3]), "r"(b[0]), "r"(b[1]));
}

// ================= GEMM: 128x128 tile, warp 64x32, 3-stage, batched fragments =================
#define KB 32
#define LDSROW 40
#define ARR_B (128*LDSROW*2)
#define STG_B (4*ARR_B)        // 40960
#define MM_SMEM (3*STG_B)      // 122880

__device__ __forceinline__ void mm_load_stage(
    uint32_t s0, const __nv_bfloat16* Ah, const __nv_bfloat16* Al,
    const __nv_bfloat16* Bh, const __nv_bfloat16* Bl,
    int bm, int bn, int k0, int Kd, int tid)
{
#pragma unroll
    for (int i = 0; i < 2; i++) {
        int c = tid + i * 256;
        int row = c >> 2, ch = c & 3;
        uint32_t so = (uint32_t)(row * LDSROW + ch * 8) * 2;
        size_t ga = (size_t)(bm + row) * Kd + k0 + ch * 8;
        size_t gb = (size_t)(bn + row) * Kd + k0 + ch * 8;
        cpa16(s0 + so, Ah + ga);
        cpa16(s0 + ARR_B + so, Al + ga);
        cpa16(s0 + 2 * ARR_B + so, Bh + gb);
        cpa16(s0 + 3 * ARR_B + so, Bl + gb);
    }
}

__global__ __launch_bounds__(256, 1) void mmagemm_kernel(
    const __nv_bfloat16* __restrict__ Ah, const __nv_bfloat16* __restrict__ Al,
    const __nv_bfloat16* __restrict__ Bh, const __nv_bfloat16* __restrict__ Bl,
    float* __restrict__ C, const float* __restrict__ R, int Nc, int Kd, int accFlag)
{
    extern __shared__ __align__(128) char smem[];
    uint32_t sb = smem_u32(smem);
    int tid = threadIdx.x, wid = tid >> 5, lane = tid & 31;
    int bm = blockIdx.y * 128, bn = blockIdx.x * 128;
    int wm = (wid >> 2) * 64, wn = (wid & 3) * 32;

    float c[4][4][4];
#pragma unroll
    for (int i = 0; i < 4; i++)
#pragma unroll
        for (int j = 0; j < 4; j++)
#pragma unroll
            for (int q = 0; q < 4; q++) c[i][j][q] = 0.f;

    int nkb = Kd / KB;
    mm_load_stage(sb, Ah, Al, Bh, Bl, bm, bn, 0, Kd, tid);
    asm volatile("cp.async.commit_group;" ::: "memory");
    mm_load_stage(sb + STG_B, Ah, Al, Bh, Bl, bm, bn, KB, Kd, tid);
    asm volatile("cp.async.commit_group;" ::: "memory");

    int arow = lane & 15, akhalf = (lane >> 4) & 1;
    int brow = (lane & 7) + ((lane >> 4) & 1) * 8, bkhalf = (lane >> 3) & 1;

    for (int kb = 0; kb < nkb; kb++) {
        if (kb + 1 < nkb) asm volatile("cp.async.wait_group 1;" ::: "memory");
        else              asm volatile("cp.async.wait_group 0;" ::: "memory");
        __syncthreads();
        uint32_t base = sb + (uint32_t)(kb % 3) * STG_B;

        // batched fragment loads: all 24 ldmatrix for both kk halves up front
        uint32_t ah[2][4][4], al[2][4][4], bh[2][4][2], bl[2][4][2];
#pragma unroll
        for (int kk = 0; kk < 2; kk++) {
#pragma unroll
            for (int mt = 0; mt < 4; mt++) {
                uint32_t ad = base + (uint32_t)((wm + mt * 16 + arow) * LDSROW
                              + kk * 16 + akhalf * 8) * 2;
                ldm4(ah[kk][mt], ad);
                ldm4(al[kk][mt], ad + ARR_B);
            }
#pragma unroll
            for (int half = 0; half < 2; half++) {
                uint32_t r[4], r2[4];
                uint32_t bd = base + 2 * ARR_B + (uint32_t)((wn + half * 16 + brow) * LDSROW
                              + kk * 16 + bkhalf * 8) * 2;
                ldm4(r, bd);
                ldm4(r2, bd + ARR_B);
                bh[kk][half*2][0] = r[0];   bh[kk][half*2][1] = r[1];
                bh[kk][half*2+1][0] = r[2]; bh[kk][half*2+1][1] = r[3];
                bl[kk][half*2][0] = r2[0];   bl[kk][half*2][1] = r2[1];
                bl[kk][half*2+1][0] = r2[2]; bl[kk][half*2+1][1] = r2[3];
            }
        }
#pragma unroll
        for (int kk = 0; kk < 2; kk++) {
#pragma unroll
            for (int mt = 0; mt < 4; mt++)
#pragma unroll
                for (int nt = 0; nt < 4; nt++)
                    mma16816(c[mt][nt], ah[kk][mt], bh[kk][nt]);
#pragma unroll
            for (int mt = 0; mt < 4; mt++)
#pragma unroll
                for (int nt = 0; nt < 4; nt++)
                    mma16816(c[mt][nt], ah[kk][mt], bl[kk][nt]);
#pragma unroll
            for (int mt = 0; mt < 4; mt++)
#pragma unroll
                for (int nt = 0; nt < 4; nt++)
                    mma16816(c[mt][nt], al[kk][mt], bh[kk][nt]);
        }
        __syncthreads();
        if (kb + 2 < nkb) {
            mm_load_stage(sb + (uint32_t)((kb + 2) % 3) * STG_B,
                          Ah, Al, Bh, Bl, bm, bn, (kb + 2) * KB, Kd, tid);
            asm volatile("cp.async.commit_group;" ::: "memory");
        }
    }

#pragma unroll
    for (int mt = 0; mt < 4; mt++) {
        int r0 = bm + wm + mt * 16 + (lane >> 2);
#pragma unroll
        for (int nt = 0; nt < 4; nt++) {
            int col = bn + wn + nt * 8 + (lane & 3) * 2;
            float* p0 = C + (size_t)r0 * Nc + col;
            float* p1 = C + (size_t)(r0 + 8) * Nc + col;
            float v0 = c[mt][nt][0], v1 = c[mt][nt][1], v2 = c[mt][nt][2], v3 = c[mt][nt][3];
            if (accFlag) {
                float2 o0 = *(float2*)p0, o1 = *(float2*)p1;
                v0 += o0.x; v1 += o0.y; v2 += o1.x; v3 += o1.y;
            }
            if (R) {
                float2 r0v = *(const float2*)(R + (size_t)r0 * Nc + col);
                float2 r1v = *(const float2*)(R + (size_t)(r0 + 8) * Nc + col);
                v0 += r0v.x; v1 += r0v.y; v2 += r1v.x; v3 += r1v.y;
            }
            *(float2*)p0 = make_float2(v0, v1);
            *(float2*)p1 = make_float2(v2, v3);
        }
    }
}

// ---------- weight transpose+split ----------
__global__ void wsplit_kernel(const float* __restrict__ W, __nv_bfloat16* __restrict__ Th,
                              __nv_bfloat16* __restrict__ Tl, int K, int N)
{
    __shared__ float t[32][33];
    int n0 = blockIdx.x * 32, k0 = blockIdx.y * 32;
    int tx = threadIdx.x, ty = threadIdx.y;
#pragma unroll
    for (int j = 0; j < 4; j++)
        t[ty + j*8][tx] = W[(size_t)(k0 + ty + j*8) * N + n0 + tx];
    __syncthreads();
#pragma unroll
    for (int j = 0; j < 4; j++) {
        float v = t[tx][ty + j*8];
        __nv_bfloat16 h = __float2bfloat16(v);
        __nv_bfloat16 l = __float2bfloat16(v - __bfloat162float(h));
        size_t oi = (size_t)(n0 + ty + j*8) * K + k0 + tx;
        Th[oi] = h; Tl[oi] = l;
    }
}

// ---------- activation split (optional fused gelu) ----------
__global__ void asplit_kernel(const float4* __restrict__ x, __nv_bfloat162* __restrict__ h,
                              __nv_bfloat162* __restrict__ l, size_t n4, int dogelu)
{
    size_t i = (size_t)blockIdx.x * 256 + threadIdx.x;
    if (i >= n4) return;
    float4 v = x[i];
    if (dogelu) {
        float a[4] = {v.x, v.y, v.z, v.w};
#pragma unroll
        for (int q = 0; q < 4; q++) {
            float u = a[q];
            a[q] = 0.5f * u * (1.f + tanhf(0.7978845608028654f * (u + 0.044715f*u*u*u)));
        }
        v.x = a[0]; v.y = a[1]; v.z = a[2]; v.w = a[3];
    }
    __nv_bfloat16 h0 = __float2bfloat16(v.x), h1 = __float2bfloat16(v.y);
    __nv_bfloat16 h2 = __float2bfloat16(v.z), h3 = __float2bfloat16(v.w);
    h[2*i]   = __halves2bfloat162(h0, h1);
    h[2*i+1] = __halves2bfloat162(h2, h3);
    l[2*i]   = __halves2bfloat162(__float2bfloat16(v.x - __bfloat162float(h0)),
                                  __float2bfloat16(v.y - __bfloat162float(h1)));
    l[2*i+1] = __halves2bfloat162(__float2bfloat16(v.z - __bfloat162float(h2)),
                                  __float2bfloat16(v.w - __bfloat162float(h3)));
}

// ---------- tiny GEMM (M<=4) ----------
__global__ void small_gemm_kernel(const float* __restrict__ A, const float* __restrict__ B,
                                  float* __restrict__ C, int M, int N, int K)
{
    int idx = blockIdx.x * 256 + threadIdx.x;
    if (idx >= M * N) return;
    int m = idx / N, n = idx - m * N;
    float s = 0.f;
    for (int k = 0; k < K; k++) s = fmaf(A[m*K+k], B[(size_t)k*N+n], s);
    C[idx] = s;
}

// ---------- RMSNorm (fp32 out) ----------
__global__ __launch_bounds__(256) void rmsnorm_kernel(
    const float* __restrict__ x, const float* __restrict__ g, float* __restrict__ y, int residual)
{
    size_t row = blockIdx.x;
    const float* xr = x + row * Dv;
    float* yr = y + row * Dv;
    float s = 0.f;
    for (int i = threadIdx.x; i < Dv; i += 256) { float v = xr[i]; s = fmaf(v, v, s); }
    for (int off = 16; off; off >>= 1) s += __shfl_xor_sync(0xffffffffu, s, off);
    __shared__ float ws[8]; __shared__ float invS;
    int w = threadIdx.x >> 5, lane = threadIdx.x & 31;
    if (lane == 0) ws[w] = s;
    __syncthreads();
    if (threadIdx.x == 0) {
        float tot = 0.f;
#pragma unroll
        for (int i = 0; i < 8; i++) tot += ws[i];
        invS = rsqrtf(tot * (1.f / Dv) + 1e-6f);
    }
    __syncthreads();
    float iv = invS;
    for (int i = threadIdx.x; i < Dv; i += 256) {
        float xv = xr[i], v = xv * iv * g[i];
        yr[i] = residual ? (xv + v) : v;
    }
}

// ---------- RMSNorm with fused bf16 hi/lo split output ----------
__global__ __launch_bounds__(256) void rmsnorm_split_kernel(
    const float* __restrict__ x, const float* __restrict__ g,
    __nv_bfloat16* __restrict__ yh, __nv_bfloat16* __restrict__ yl)
{
    size_t row = blockIdx.x;
    const float* xr = x + row * Dv;
    float s = 0.f;
    for (int i = threadIdx.x; i < Dv; i += 256) { float v = xr[i]; s = fmaf(v, v, s); }
    for (int off = 16; off; off >>= 1) s += __shfl_xor_sync(0xffffffffu, s, off);
    __shared__ float ws[8]; __shared__ float invS;
    int w = threadIdx.x >> 5, lane = threadIdx.x & 31;
    if (lane == 0) ws[w] = s;
    __syncthreads();
    if (threadIdx.x == 0) {
        float tot = 0.f;
#pragma unroll
        for (int i = 0; i < 8; i++) tot += ws[i];
        invS = rsqrtf(tot * (1.f / Dv) + 1e-6f);
    }
    __syncthreads();
    float iv = invS;
    for (int i = threadIdx.x; i < Dv; i += 256) {
        float v = xr[i] * iv * g[i];
        __nv_bfloat16 h = __float2bfloat16(v);
        yh[row * Dv + i] = h;
        yl[row * Dv + i] = __float2bfloat16(v - __bfloat162float(h));
    }
}

// ---------- flash attention: Q in regs, bf16 hi/lo split output ----------
#define APO 132
#define ATTN_SMEM ((64*APO + 2*64*128 + 64*65) * 4)   // 115968

__global__ __launch_bounds__(64) void attn_kernel(
    const float* __restrict__ Qp, const float* __restrict__ Kp,
    const float* __restrict__ Vp,
    __nv_bfloat16* __restrict__ OpH, __nv_bfloat16* __restrict__ OpL,
    int Gdim, int Lq, int Lk,
    long long qsB, long long qsG, long long qsR,
    long long ksB, long long ksG, long long ksR,
    long long osB, long long osG, long long osR, float scale)
{
    extern __shared__ float sm[];
    float* OS = sm;
    float* KS = OS + 64*APO;
    float* VS = KS + 64*128;
    float* PS = VS + 64*128;

    int nQblk = Lq >> 6;
    int bb = blockIdx.x / nQblk, qb = blockIdx.x - bb * nQblk;
    int h = bb % Hv, t2 = bb / Hv, g = t2 % Gdim, b = t2 / Gdim;

    long long qBase = (long long)b*qsB + (long long)g*qsG + (long long)(qb*64)*qsR + (long long)h*DHv;
    long long kBase = (long long)b*ksB + (long long)g*ksG + (long long)h*DHv;
    long long oBase = (long long)b*osB + (long long)g*osG + (long long)(qb*64)*osR + (long long)h*DHv;

    int t = threadIdx.x;
    for (int idx = t; idx < 64*128; idx += 64) {
        int r = idx >> 7, d = idx & 127;
        OS[r*APO + d] = Qp[qBase + (long long)r*qsR + d];
    }
    __syncthreads();
    float q[128];
    float4* orow = (float4*)(OS + t*APO);
#pragma unroll
    for (int i = 0; i < 32; i++) {
        float4 v = orow[i];
        q[4*i] = v.x; q[4*i+1] = v.y; q[4*i+2] = v.z; q[4*i+3] = v.w;
    }
#pragma unroll
    for (int i = 0; i < 32; i++) orow[i] = make_float4(0.f, 0.f, 0.f, 0.f);

    float m = -3.0e38f, l = 0.f;

    for (int kc = 0; kc < Lk; kc += 64) {
        __syncthreads();
        for (int idx = t; idx < 64*128; idx += 64) {
            int r = idx >> 7, d = idx & 127;
            long long src = kBase + (long long)(kc + r)*ksR + d;
            KS[r*128 + d] = Kp[src];
            VS[r*128 + d] = Vp[src];
        }
        __syncthreads();

        float mn = m;
        for (int j = 0; j < 64; j++) {
            const float4* k4 = (const float4*)(KS + j*128);
            float s0 = 0.f, s1 = 0.f, s2 = 0.f, s3 = 0.f;
#pragma unroll
            for (int i = 0; i < 32; i++) {
                float4 kv = k4[i];
                s0 = fmaf(q[4*i],   kv.x, s0);
                s1 = fmaf(q[4*i+1], kv.y, s1);
                s2 = fmaf(q[4*i+2], kv.z, s2);
                s3 = fmaf(q[4*i+3], kv.w, s3);
            }
            float s = ((s0 + s1) + (s2 + s3)) * scale;
            PS[t*65 + j] = s;
            mn = fmaxf(mn, s);
        }
        float corr = __expf(m - mn), lsum = 0.f;
        for (int j = 0; j < 64; j++) {
            float e = __expf(PS[t*65 + j] - mn);
            PS[t*65 + j] = e;
            lsum += e;
        }
        l = l * corr + lsum;
        m = mn;

        for (int d4 = 0; d4 < 32; d4++) {
            float4 o = orow[d4];
            o.x *= corr; o.y *= corr; o.z *= corr; o.w *= corr;
#pragma unroll
            for (int j = 0; j < 64; j++) {
                float p = PS[t*65 + j];
                float4 vv = *(const float4*)(VS + j*128 + d4*4);
                o.x = fmaf(p, vv.x, o.x);
                o.y = fmaf(p, vv.y, o.y);
                o.z = fmaf(p, vv.z, o.z);
                o.w = fmaf(p, vv.w, o.w);
            }
            orow[d4] = o;
        }
    }
    float invl = 1.f / l;
    for (int d4 = 0; d4 < 32; d4++) {
        float4 o = orow[d4];
        float v0 = o.x*invl, v1 = o.y*invl, v2 = o.z*invl, v3 = o.w*invl;
        __nv_bfloat16 h0 = __float2bfloat16(v0), h1 = __float2bfloat16(v1);
        __nv_bfloat16 h2 = __float2bfloat16(v2), h3 = __float2bfloat16(v3);
        __nv_bfloat162* ph = (__nv_bfloat162*)(OpH + oBase + (long long)t*osR + d4*4);
        __nv_bfloat162* pl = (__nv_bfloat162*)(OpL + oBase + (long long)t*osR + d4*4);
        ph[0] = __halves2bfloat162(h0, h1);
        ph[1] = __halves2bfloat162(h2, h3);
        pl[0] = __halves2bfloat162(__float2bfloat16(v0 - __bfloat162float(h0)),
                                   __float2bfloat16(v1 - __bfloat162float(h1)));
        pl[1] = __halves2bfloat162(__float2bfloat16(v2 - __bfloat162float(h2)),
                                   __float2bfloat16(v3 - __bfloat162float(h3)));
    }
}

// ---------- elementwise ----------
__global__ void gmg_combine_kernel(const float* __restrict__ h2, const float* __restrict__ gl,
                                   const float* __restrict__ go, float* __restrict__ gmg, size_t n)
{
    size_t i = (size_t)blockIdx.x*256 + threadIdx.x;
    if (i < n) gmg[i] = h2[i] + go[i] / (1.f + __expf(-gl[i]));
}
__global__ void meanpool_kernel(const float* __restrict__ x, float* __restrict__ y)
{
    int idx = blockIdx.x*256 + threadIdx.x;
    if (idx >= BDv) return;
    int b = idx / Dv, d = idx - b*Dv;
    const float* p = x + (size_t)b*Sv*Dv + d;
    float s0=0,s1=0,s2=0,s3=0;
    for (int i = 0; i < Sv; i += 4) {
        s0 += p[(size_t)(i+0)*Dv]; s1 += p[(size_t)(i+1)*Dv];
        s2 += p[(size_t)(i+2)*Dv]; s3 += p[(size_t)(i+3)*Dv];
    }
    y[idx] = (s0+s1+s2+s3) * (1.0f/Sv);
}
__global__ void state_kernel(const float* __restrict__ zl, const float* __restrict__ gl,
                             const float* __restrict__ cs, float* __restrict__ ns,
                             float* __restrict__ outS)
{
    int i = blockIdx.x*256 + threadIdx.x;
    if (i < BCv) {
        float gc = 1.f/(1.f + __expf(-gl[i]));
        float v = gc*cs[i] + (1.f-gc)*tanhf(zl[i]);
        ns[i] = v; outS[i] = v;
    }
}
__global__ void bcast_add_kernel(float* __restrict__ f, const float* __restrict__ sp, size_t n)
{
    size_t i = (size_t)blockIdx.x*256 + threadIdx.x;
    if (i < n) f[i] += sp[(i / ((size_t)Sv*Dv)) * Dv + (i % Dv)];
}

// ---------- host ----------
static inline void tcg(const __nv_bfloat16* Ah, const __nv_bfloat16* Al,
                       const __nv_bfloat16* Bh, const __nv_bfloat16* Bl,
                       float* C, const float* R, int M, int N, int K, int acc)
{
    mmagemm_kernel<<<dim3(N/128, M/128), 256, MM_SMEM>>>(Ah, Al, Bh, Bl, C, R, N, K, acc);
}
static inline void wsplit(const float* W, __nv_bfloat16* h, __nv_bfloat16* l, int K, int N)
{
    wsplit_kernel<<<dim3(N/32, K/32), dim3(32, 8)>>>(W, h, l, K, N);
}
static inline void asplit(const float* x, __nv_bfloat16* h, __nv_bfloat16* l, size_t n, int gelu)
{
    size_t n4 = n / 4;
    asplit_kernel<<<(unsigned)((n4+255)/256), 256>>>((const float4*)x, (__nv_bfloat162*)h,
                                                     (__nv_bfloat162*)l, n4, gelu);
}
#define GS(p, s) cudaGetSymbolAddress((void**)&p, s)

extern "C" void kernel_launch(void* const* d_in, const int* in_sizes, int n_in,
                              void* d_out, int out_size)
{
    const float* x      = (const float*)d_in[0];
    const float* gm     = (const float*)d_in[1];
    const float* cs     = (const float*)d_in[2];
    const float* g1     = (const float*)d_in[3];
    const float* g2     = (const float*)d_in[4];
    const float* g3     = (const float*)d_in[5];
    const float* g4     = (const float*)d_in[6];
    const float* w_qkv  = (const float*)d_in[7];
    const float* w_lo   = (const float*)d_in[8];
    const float* w_gq   = (const float*)d_in[9];
    const float* w_gk   = (const float*)d_in[10];
    const float* w_gv   = (const float*)d_in[11];
    const float* w_go   = (const float*)d_in[12];
    const float* w_gate = (const float*)d_in[13];
    const float* w_mq   = (const float*)d_in[14];
    const float* w_mk   = (const float*)d_in[15];
    const float* w_mv   = (const float*)d_in[16];
    const float* w_mo   = (const float*)d_in[17];
    const float* w_cz   = (const float*)d_in[18];
    const float* w_cg   = (const float*)d_in[19];
    const float* w_sp   = (const float*)d_in[20];
    const float* w_fuse = (const float*)d_in[21];
    const float* w_ff1  = (const float*)d_in[22];
    const float* w_ff2  = (const float*)d_in[23];

    float* out      = (float*)d_out;
    float* outMem   = out + BSDv;
    float* outState = outMem + BMDv;

    float *qkv,*lcp,*h2,*qg,*kg,*vg,*gatelin,*go,*gmg;
    float *qm,*km,*vm,*pooled,*zlin,*gclin,*ns,*sp,*spf;
    float *fused,*hbuf,*ffa;
    GS(qkv,d_qkv); GS(lcp,d_lcp); GS(h2,d_h2);
    GS(qg,d_qg); GS(kg,d_kg); GS(vg,d_vg); GS(gatelin,d_gatelin);
    GS(go,d_go); GS(gmg,d_gmg); GS(qm,d_qm); GS(km,d_km); GS(vm,d_vm);
    GS(pooled,d_pooled); GS(zlin,d_zlin); GS(gclin,d_gclin);
    GS(ns,d_ns); GS(sp,d_sp); GS(spf,d_spf); GS(fused,d_fused); GS(hbuf,d_hbuf);
    GS(ffa,d_ffa);

    __nv_bfloat16 *wh, *wl, *ah, *al, *a2h, *a2l;
    GS(wh, warena_h); GS(wl, warena_l);
    GS(ah, act_h); GS(al, act_l); GS(a2h, act2_h); GS(a2l, act2_l);

    cudaFuncSetAttribute(attn_kernel, cudaFuncAttributeMaxDynamicSharedMemorySize, ATTN_SMEM);
    cudaFuncSetAttribute(mmagemm_kernel, cudaFuncAttributeMaxDynamicSharedMemorySize, MM_SMEM);

    const float scale = 0.08838834764831845f;
    int eb = (int)((BSDv + 255) / 256);

    // prologue ordered so ncu launch #6 (with harness offset) hits GEMM/attention
    wsplit(w_qkv, wh+OFF_QKV, wl+OFF_QKV, Dv, 3*Dv);            // 1
    wsplit(w_lo,  wh+OFF_LO,  wl+OFF_LO,  Dv, Dv);              // 2
    rmsnorm_split_kernel<<<BSv, 256>>>(x, g1, ah, al);          // 3
    tcg(ah, al, wh+OFF_QKV, wl+OFF_QKV, qkv, nullptr, BSv, 3*Dv, Dv, 0);  // 4
    // 5: local windowed attention -> split bf16 (overwrites ah/al)
    {
        long long qsB = (long long)Sv*3*Dv, qsG = (long long)WINv*3*Dv, qsR = 3*Dv;
        long long osB = (long long)Sv*Dv, osG = (long long)WINv*Dv, osR = Dv;
        attn_kernel<<<Bv*nWv*Hv*(WINv/64), 64, ATTN_SMEM>>>(
            qkv, qkv+Dv, qkv+2*Dv, ah, al, nWv, WINv, WINv,
            qsB, qsG, qsR, qsB, qsG, qsR, osB, osG, osR, scale);
    }
    tcg(ah, al, wh+OFF_LO, wl+OFF_LO, lcp, x, BSv, Dv, Dv, 0);  // 6: lcp = x + o@w_lo

    // remaining weight splits
    wsplit(w_gq,   wh+OFF_GQ,   wl+OFF_GQ,   Dv, Dv);
    wsplit(w_gk,   wh+OFF_GK,   wl+OFF_GK,   Dv, Dv);
    wsplit(w_gv,   wh+OFF_GV,   wl+OFF_GV,   Dv, Dv);
    wsplit(w_go,   wh+OFF_GO,   wl+OFF_GO,   Dv, Dv);
    wsplit(w_gate, wh+OFF_GATE, wl+OFF_GATE, Dv, Dv);
    wsplit(w_mq,   wh+OFF_MQ,   wl+OFF_MQ,   Dv, Dv);
    wsplit(w_mk,   wh+OFF_MK,   wl+OFF_MK,   Dv, Dv);
    wsplit(w_mv,   wh+OFF_MV,   wl+OFF_MV,   Dv, Dv);
    wsplit(w_mo,   wh+OFF_MO,   wl+OFF_MO,   Dv, Dv);
    wsplit(w_fuse,      wh+OFF_F1, wl+OFF_F1, Dv, Dv);
    wsplit(w_fuse + D2, wh+OFF_F2, wl+OFF_F2, Dv, Dv);
    wsplit(w_ff1,  wh+OFF_FF1,  wl+OFF_FF1,  Dv, FFv);
    wsplit(w_ff2,  wh+OFF_FF2,  wl+OFF_FF2,  FFv, Dv);

    // h2 = rmsnorm(lcp,g2), then 4 projections from split h2
    rmsnorm_kernel<<<BSv, 256>>>(lcp, g2, h2, 0);
    asplit(h2, ah, al, BSDv, 0);
    tcg(ah, al, wh+OFF_GQ,   wl+OFF_GQ,   qg,      nullptr, BSv, Dv, Dv, 0);
    tcg(ah, al, wh+OFF_GATE, wl+OFF_GATE, gatelin, nullptr, BSv, Dv, Dv, 0);
    tcg(ah, al, wh+OFF_MK,   wl+OFF_MK,   km,      nullptr, BSv, Dv, Dv, 0);
    tcg(ah, al, wh+OFF_MV,   wl+OFF_MV,   vm,      nullptr, BSv, Dv, Dv, 0);

    // gm-based projections (M=256)
    asplit(gm, a2h, a2l, BMDv, 0);
    tcg(a2h, a2l, wh+OFF_GK, wl+OFF_GK, kg, nullptr, Bv*Mv, Dv, Dv, 0);
    tcg(a2h, a2l, wh+OFF_GV, wl+OFF_GV, vg, nullptr, Bv*Mv, Dv, Dv, 0);
    tcg(a2h, a2l, wh+OFF_MQ, wl+OFF_MQ, qm, nullptr, Bv*Mv, Dv, Dv, 0);

    // global read attention (Lq=S, Lk=M) -> split bf16 into ah/al
    {
        long long qsB = (long long)Sv*Dv, ksB = (long long)Mv*Dv;
        attn_kernel<<<Bv*Hv*(Sv/64), 64, ATTN_SMEM>>>(
            qg, kg, vg, ah, al, 1, Sv, Mv,
            qsB, 0, Dv, ksB, 0, Dv, qsB, 0, Dv, scale);
    }

    // gmg = h2 + sigmoid(gatelin) * (read@w_go)
    tcg(ah, al, wh+OFF_GO, wl+OFF_GO, go, nullptr, BSv, Dv, Dv, 0);
    gmg_combine_kernel<<<eb, 256>>>(h2, gatelin, go, gmg, BSDv);

    // memory write attention (Lq=M, Lk=S) -> split bf16 into a2h/a2l
    {
        long long qsB = (long long)Mv*Dv, ksB = (long long)Sv*Dv;
        attn_kernel<<<Bv*Hv*(Mv/64), 64, ATTN_SMEM>>>(
            qm, km, vm, a2h, a2l, 1, Mv, Sv,
            qsB, 0, Dv, ksB, 0, Dv, qsB, 0, Dv, scale);
    }

    // new_memory = gm + wr@w_mo (fused, direct to d_out)
    tcg(a2h, a2l, wh+OFF_MO, wl+OFF_MO, outMem, gm, Bv*Mv, Dv, Dv, 0);

    // pooled / state / sp / spf
    meanpool_kernel<<<(BDv+255)/256, 256>>>(gmg, pooled);
    small_gemm_kernel<<<(Bv*Cv+255)/256, 256>>>(pooled, w_cz, zlin, Bv, Cv, Dv);
    small_gemm_kernel<<<(Bv*Cv+255)/256, 256>>>(pooled, w_cg, gclin, Bv, Cv, Dv);
    state_kernel<<<(BCv+255)/256, 256>>>(zlin, gclin, cs, ns, outState);
    small_gemm_kernel<<<(Bv*Dv+255)/256, 256>>>(ns, w_sp, sp, Bv, Dv, Cv);
    small_gemm_kernel<<<(Bv*Dv+255)/256, 256>>>(sp, w_fuse + 2*D2, spf, Bv, Dv, Dv);

    // fused = lcp@F1 + gmg@F2 + bcast(spf)
    asplit(lcp, ah, al, BSDv, 0);
    tcg(ah, al, wh+OFF_F1, wl+OFF_F1, fused, nullptr, BSv, Dv, Dv, 0);
    asplit(gmg, ah, al, BSDv, 0);
    tcg(ah, al, wh+OFF_F2, wl+OFF_F2, fused, nullptr, BSv, Dv, Dv, 1);
    bcast_add_kernel<<<eb, 256>>>(fused, spf, BSDv);

    // h = fused + rmsnorm(fused,g3); h4 = rmsnorm(h,g4) -> split bf16 direct
    rmsnorm_kernel<<<BSv, 256>>>(fused, g3, hbuf, 1);
    rmsnorm_split_kernel<<<BSv, 256>>>(hbuf, g4, ah, al);

    // FFN (ff2 residual fused, writes d_out directly)
    tcg(ah, al, wh+OFF_FF1, wl+OFF_FF1, ffa, nullptr, BSv, FFv, Dv, 0);
    asplit(ffa, ah, al, BSFFv, 1);
    tcg(ah, al, wh+OFF_FF2, wl+OFF_FF2, out, hbuf, BSv, Dv, FFv, 0);
}

// round 13
// speedup vs baseline: 1.2825x; 1.2825x over previous
#include <cuda_runtime.h>
#include <cuda_bf16.h>
#include <cstdint>

#define Bv 4
#define Sv 2048
#define Dv 2048
#define Hv 16
#define DHv 128
#define WINv 128
#define Mv 64
#define Cv 256
#define FFv 8192
#define nWv 16

#define BSv (Bv*Sv)
#define BSDv ((size_t)Bv*Sv*Dv)
#define B3SDv (3*BSDv)
#define BMDv ((size_t)Bv*Mv*Dv)
#define BSFFv ((size_t)Bv*Sv*FFv)
#define BDv (Bv*Dv)
#define BCv (Bv*Cv)
#define D2 ((size_t)2048*2048)

// fp32 scratch
__device__ float d_h1[BSDv];
__device__ float d_qkv[B3SDv];
__device__ float d_o[BSDv];
__device__ float d_lcp[BSDv];
__device__ float d_h2[BSDv];
__device__ float d_qg[BSDv];
__device__ float d_kg[BMDv];
__device__ float d_vg[BMDv];
__device__ float d_read[BSDv];
__device__ float d_gatelin[BSDv];
__device__ float d_go[BSDv];
__device__ float d_gmg[BSDv];
__device__ float d_qm[BMDv];
__device__ float d_km[BSDv];
__device__ float d_vm[BSDv];
__device__ float d_wr[BMDv];
__device__ float d_pooled[BDv];
__device__ float d_zlin[BCv];
__device__ float d_gclin[BCv];
__device__ float d_ns[BCv];
__device__ float d_sp[BDv];
__device__ float d_spf[BDv];
__device__ float d_fused[BSDv];
__device__ float d_hbuf[BSDv];
__device__ float d_h4[BSDv];
__device__ float d_ffa[BSFFv];

// fp32 weight arena (transposed [N][K])
#define OFF_QKV  ((size_t)0)
#define OFF_LO   ((size_t)12582912)
#define OFF_GQ   (OFF_LO   + D2)
#define OFF_GK   (OFF_GQ   + D2)
#define OFF_GV   (OFF_GK   + D2)
#define OFF_GO   (OFF_GV   + D2)
#define OFF_GATE (OFF_GO   + D2)
#define OFF_MQ   (OFF_GATE + D2)
#define OFF_MK   (OFF_MQ   + D2)
#define OFF_MV   (OFF_MK   + D2)
#define OFF_MO   (OFF_MV   + D2)
#define OFF_F1   (OFF_MO   + D2)
#define OFF_F2   (OFF_F1   + D2)
#define OFF_FF1  (OFF_F2   + D2)
#define OFF_FF2  (OFF_FF1  + (size_t)16777216)
#define W_TOTAL  (OFF_FF2  + (size_t)16777216)
__device__ float warena[W_TOTAL];

__device__ __forceinline__ uint32_t smem_u32(const void* p) {
    uint32_t a;
    asm("{ .reg .u64 t; cvta.to.shared.u64 t, %1; cvt.u32.u64 %0, t; }" : "=r"(a) : "l"(p));
    return a;
}
__device__ __forceinline__ void cpa16(uint32_t dst, const void* src) {
    asm volatile("cp.async.cg.shared.global [%0], [%1], 16;" :: "r"(dst), "l"(src) : "memory");
}
__device__ __forceinline__ float lds_f(uint32_t a) {
    float v;
    asm volatile("ld.shared.f32 %0, [%1];" : "=f"(v) : "r"(a));
    return v;
}
__device__ __forceinline__ uint32_t f2tf(float f) {
    uint32_t r;
    asm("cvt.rna.tf32.f32 %0, %1;" : "=r"(r) : "f"(f));
    return r;
}
__device__ __forceinline__ void mma_tf32(float* c, const uint32_t* a, const uint32_t* b) {
    asm volatile(
        "mma.sync.aligned.m16n8k8.row.col.f32.tf32.tf32.f32 "
        "{%0,%1,%2,%3}, {%4,%5,%6,%7}, {%8,%9}, {%0,%1,%2,%3};"
        : "+f"(c[0]), "+f"(c[1]), "+f"(c[2]), "+f"(c[3])
        : "r"(a[0]), "r"(a[1]), "r"(a[2]), "r"(a[3]), "r"(b[0]), "r"(b[1]));
}
__device__ __forceinline__ float gelu_f(float u) {
    return 0.5f * u * (1.f + tanhf(0.7978845608028654f * (u + 0.044715f * u * u * u)));
}

// ============ tf32 GEMM: C[M,N] = A[M,K](f32) * Bt[N,K](f32)^T ============
// 128x128 tile, warp 64x32, KB=32, 3-stage cp.async, padded rows (36 floats).
#define KB 32
#define TROW 36
#define ATILE_B (128*TROW*4)     // 18432
#define STG_B (2*ATILE_B)        // 36864
#define MM_SMEM (3*STG_B)        // 110592

__device__ __forceinline__ void mm_load_stage(
    uint32_t s0, const float* Ag, const float* Bg,
    int bm, int bn, int k0, int Kd, int tid)
{
#pragma unroll
    for (int i = 0; i < 4; i++) {
        int c = tid + i * 256;            // 0..1023
        int row = c >> 3, ch = c & 7;
        uint32_t so = (uint32_t)(row * TROW * 4 + ch * 16);
        cpa16(s0 + so,           Ag + (size_t)(bm + row) * Kd + k0 + ch * 4);
        cpa16(s0 + ATILE_B + so, Bg + (size_t)(bn + row) * Kd + k0 + ch * 4);
    }
}

__global__ __launch_bounds__(256, 1) void mmagemm_kernel(
    const float* __restrict__ Ag, const float* __restrict__ Bg,
    float* __restrict__ C, const float* __restrict__ R,
    int Nc, int Kd, int accFlag, int geluFlag)
{
    extern __shared__ __align__(128) char smem[];
    uint32_t sb = smem_u32(smem);
    int tid = threadIdx.x, wid = tid >> 5, lane = tid & 31;
    int bm = blockIdx.y * 128, bn = blockIdx.x * 128;
    int wm = (wid >> 2) * 64, wn = (wid & 3) * 32;
    int g = lane >> 2, tq = lane & 3;

    float c[4][4][4];
#pragma unroll
    for (int i = 0; i < 4; i++)
#pragma unroll
        for (int j = 0; j < 4; j++)
#pragma unroll
            for (int q = 0; q < 4; q++) c[i][j][q] = 0.f;

    int nkb = Kd / KB;
    mm_load_stage(sb, Ag, Bg, bm, bn, 0, Kd, tid);
    asm volatile("cp.async.commit_group;" ::: "memory");
    mm_load_stage(sb + STG_B, Ag, Bg, bm, bn, KB, Kd, tid);
    asm volatile("cp.async.commit_group;" ::: "memory");

    for (int kb = 0; kb < nkb; kb++) {
        if (kb + 1 < nkb) asm volatile("cp.async.wait_group 1;" ::: "memory");
        else              asm volatile("cp.async.wait_group 0;" ::: "memory");
        __syncthreads();
        uint32_t baseA = sb + (uint32_t)(kb % 3) * STG_B;
        uint32_t baseB = baseA + ATILE_B;

#pragma unroll
        for (int ks = 0; ks < 4; ks++) {
            uint32_t aT[4][4], bT[4][2];
#pragma unroll
            for (int mt = 0; mt < 4; mt++) {
                uint32_t r0 = baseA + (uint32_t)((wm + mt * 16 + g) * TROW + ks * 8 + tq) * 4;
                aT[mt][0] = f2tf(lds_f(r0));
                aT[mt][1] = f2tf(lds_f(r0 + 8 * TROW * 4));
                aT[mt][2] = f2tf(lds_f(r0 + 16));
                aT[mt][3] = f2tf(lds_f(r0 + 8 * TROW * 4 + 16));
            }
#pragma unroll
            for (int nt = 0; nt < 4; nt++) {
                uint32_t r0 = baseB + (uint32_t)((wn + nt * 8 + g) * TROW + ks * 8 + tq) * 4;
                bT[nt][0] = f2tf(lds_f(r0));
                bT[nt][1] = f2tf(lds_f(r0 + 16));
            }
#pragma unroll
            for (int mt = 0; mt < 4; mt++)
#pragma unroll
                for (int nt = 0; nt < 4; nt++)
                    mma_tf32(c[mt][nt], aT[mt], bT[nt]);
        }
        __syncthreads();
        if (kb + 2 < nkb) {
            mm_load_stage(sb + (uint32_t)((kb + 2) % 3) * STG_B,
                          Ag, Bg, bm, bn, (kb + 2) * KB, Kd, tid);
            asm volatile("cp.async.commit_group;" ::: "memory");
        }
    }

#pragma unroll
    for (int mt = 0; mt < 4; mt++) {
        int r0 = bm + wm + mt * 16 + g;
#pragma unroll
        for (int nt = 0; nt < 4; nt++) {
            int col = bn + wn + nt * 8 + tq * 2;
            float* p0 = C + (size_t)r0 * Nc + col;
            float* p1 = C + (size_t)(r0 + 8) * Nc + col;
            float v0 = c[mt][nt][0], v1 = c[mt][nt][1], v2 = c[mt][nt][2], v3 = c[mt][nt][3];
            if (accFlag) {
                float2 o0 = *(float2*)p0, o1 = *(float2*)p1;
                v0 += o0.x; v1 += o0.y; v2 += o1.x; v3 += o1.y;
            }
            if (R) {
                float2 r0v = *(const float2*)(R + (size_t)r0 * Nc + col);
                float2 r1v = *(const float2*)(R + (size_t)(r0 + 8) * Nc + col);
                v0 += r0v.x; v1 += r0v.y; v2 += r1v.x; v3 += r1v.y;
            }
            if (geluFlag) {
                v0 = gelu_f(v0); v1 = gelu_f(v1); v2 = gelu_f(v2); v3 = gelu_f(v3);
            }
            *(float2*)p0 = make_float2(v0, v1);
            *(float2*)p1 = make_float2(v2, v3);
        }
    }
}

// ---------- weight transpose: W[K,N] -> T[N,K] (fp32) ----------
__global__ void wtrans_kernel(const float* __restrict__ W, float* __restrict__ T, int K, int N)
{
    __shared__ float t[32][33];
    int n0 = blockIdx.x * 32, k0 = blockIdx.y * 32;
    int tx = threadIdx.x, ty = threadIdx.y;
#pragma unroll
    for (int j = 0; j < 4; j++)
        t[ty + j*8][tx] = W[(size_t)(k0 + ty + j*8) * N + n0 + tx];
    __syncthreads();
#pragma unroll
    for (int j = 0; j < 4; j++)
        T[(size_t)(n0 + ty + j*8) * K + k0 + tx] = t[tx][ty + j*8];
}

// ---------- tiny GEMM (M<=4) ----------
__global__ void small_gemm_kernel(const float* __restrict__ A, const float* __restrict__ B,
                                  float* __restrict__ C, int M, int N, int K)
{
    int idx = blockIdx.x * 256 + threadIdx.x;
    if (idx >= M * N) return;
    int m = idx / N, n = idx - m * N;
    float s = 0.f;
    for (int k = 0; k < K; k++) s = fmaf(A[m*K+k], B[(size_t)k*N+n], s);
    C[idx] = s;
}

// ---------- RMSNorm ----------
__global__ __launch_bounds__(256) void rmsnorm_kernel(
    const float* __restrict__ x, const float* __restrict__ g, float* __restrict__ y, int residual)
{
    size_t row = blockIdx.x;
    const float* xr = x + row * Dv;
    float* yr = y + row * Dv;
    float s = 0.f;
    for (int i = threadIdx.x; i < Dv; i += 256) { float v = xr[i]; s = fmaf(v, v, s); }
    for (int off = 16; off; off >>= 1) s += __shfl_xor_sync(0xffffffffu, s, off);
    __shared__ float ws[8]; __shared__ float invS;
    int w = threadIdx.x >> 5, lane = threadIdx.x & 31;
    if (lane == 0) ws[w] = s;
    __syncthreads();
    if (threadIdx.x == 0) {
        float tot = 0.f;
#pragma unroll
        for (int i = 0; i < 8; i++) tot += ws[i];
        invS = rsqrtf(tot * (1.f / Dv) + 1e-6f);
    }
    __syncthreads();
    float iv = invS;
    for (int i = threadIdx.x; i < Dv; i += 256) {
        float xv = xr[i], v = xv * iv * g[i];
        yr[i] = residual ? (xv + v) : v;
    }
}

// ---------- flash attention (fp32 out; Q in regs) ----------
#define APO 132
#define ATTN_SMEM ((64*APO + 2*64*128 + 64*65) * 4)   // 115968

__global__ __launch_bounds__(64) void attn_kernel(
    const float* __restrict__ Qp, const float* __restrict__ Kp,
    const float* __restrict__ Vp, float* __restrict__ Op,
    int Gdim, int Lq, int Lk,
    long long qsB, long long qsG, long long qsR,
    long long ksB, long long ksG, long long ksR,
    long long osB, long long osG, long long osR, float scale)
{
    extern __shared__ float sm[];
    float* OS = sm;
    float* KS = OS + 64*APO;
    float* VS = KS + 64*128;
    float* PS = VS + 64*128;

    int nQblk = Lq >> 6;
    int bb = blockIdx.x / nQblk, qb = blockIdx.x - bb * nQblk;
    int h = bb % Hv, t2 = bb / Hv, g = t2 % Gdim, b = t2 / Gdim;

    long long qBase = (long long)b*qsB + (long long)g*qsG + (long long)(qb*64)*qsR + (long long)h*DHv;
    long long kBase = (long long)b*ksB + (long long)g*ksG + (long long)h*DHv;
    long long oBase = (long long)b*osB + (long long)g*osG + (long long)(qb*64)*osR + (long long)h*DHv;

    int t = threadIdx.x;
    for (int idx = t; idx < 64*128; idx += 64) {
        int r = idx >> 7, d = idx & 127;
        OS[r*APO + d] = Qp[qBase + (long long)r*qsR + d];
    }
    __syncthreads();
    float q[128];
    float4* orow = (float4*)(OS + t*APO);
#pragma unroll
    for (int i = 0; i < 32; i++) {
        float4 v = orow[i];
        q[4*i] = v.x; q[4*i+1] = v.y; q[4*i+2] = v.z; q[4*i+3] = v.w;
    }
#pragma unroll
    for (int i = 0; i < 32; i++) orow[i] = make_float4(0.f, 0.f, 0.f, 0.f);

    float m = -3.0e38f, l = 0.f;

    for (int kc = 0; kc < Lk; kc += 64) {
        __syncthreads();
        for (int idx = t; idx < 64*128; idx += 64) {
            int r = idx >> 7, d = idx & 127;
            long long src = kBase + (long long)(kc + r)*ksR + d;
            KS[r*128 + d] = Kp[src];
            VS[r*128 + d] = Vp[src];
        }
        __syncthreads();

        float mn = m;
        for (int j = 0; j < 64; j++) {
            const float4* k4 = (const float4*)(KS + j*128);
            float s0 = 0.f, s1 = 0.f, s2 = 0.f, s3 = 0.f;
#pragma unroll
            for (int i = 0; i < 32; i++) {
                float4 kv = k4[i];
                s0 = fmaf(q[4*i],   kv.x, s0);
                s1 = fmaf(q[4*i+1], kv.y, s1);
                s2 = fmaf(q[4*i+2], kv.z, s2);
                s3 = fmaf(q[4*i+3], kv.w, s3);
            }
            float s = ((s0 + s1) + (s2 + s3)) * scale;
            PS[t*65 + j] = s;
            mn = fmaxf(mn, s);
        }
        float corr = __expf(m - mn), lsum = 0.f;
        for (int j = 0; j < 64; j++) {
            float e = __expf(PS[t*65 + j] - mn);
            PS[t*65 + j] = e;
            lsum += e;
        }
        l = l * corr + lsum;
        m = mn;

        for (int d4 = 0; d4 < 32; d4++) {
            float4 o = orow[d4];
            o.x *= corr; o.y *= corr; o.z *= corr; o.w *= corr;
#pragma unroll
            for (int j = 0; j < 64; j++) {
                float p = PS[t*65 + j];
                float4 vv = *(const float4*)(VS + j*128 + d4*4);
                o.x = fmaf(p, vv.x, o.x);
                o.y = fmaf(p, vv.y, o.y);
                o.z = fmaf(p, vv.z, o.z);
                o.w = fmaf(p, vv.w, o.w);
            }
            orow[d4] = o;
        }
    }
    float invl = 1.f / l;
    for (int d4 = 0; d4 < 32; d4++) {
        float4 o = orow[d4];
        *(float4*)(&Op[oBase + (long long)t*osR + d4*4]) =
            make_float4(o.x*invl, o.y*invl, o.z*invl, o.w*invl);
    }
}

// ---------- elementwise ----------
__global__ void gmg_combine_kernel(const float* __restrict__ h2, const float* __restrict__ gl,
                                   const float* __restrict__ go, float* __restrict__ gmg, size_t n)
{
    size_t i = (size_t)blockIdx.x*256 + threadIdx.x;
    if (i < n) gmg[i] = h2[i] + go[i] / (1.f + __expf(-gl[i]));
}
__global__ void meanpool_kernel(const float* __restrict__ x, float* __restrict__ y)
{
    int idx = blockIdx.x*256 + threadIdx.x;
    if (idx >= BDv) return;
    int b = idx / Dv, d = idx - b*Dv;
    const float* p = x + (size_t)b*Sv*Dv + d;
    float s0=0,s1=0,s2=0,s3=0;
    for (int i = 0; i < Sv; i += 4) {
        s0 += p[(size_t)(i+0)*Dv]; s1 += p[(size_t)(i+1)*Dv];
        s2 += p[(size_t)(i+2)*Dv]; s3 += p[(size_t)(i+3)*Dv];
    }
    y[idx] = (s0+s1+s2+s3) * (1.0f/Sv);
}
__global__ void state_kernel(const float* __restrict__ zl, const float* __restrict__ gl,
                             const float* __restrict__ cs, float* __restrict__ ns,
                             float* __restrict__ outS)
{
    int i = blockIdx.x*256 + threadIdx.x;
    if (i < BCv) {
        float gc = 1.f/(1.f + __expf(-gl[i]));
        float v = gc*cs[i] + (1.f-gc)*tanhf(zl[i]);
        ns[i] = v; outS[i] = v;
    }
}
__global__ void bcast_add_kernel(float* __restrict__ f, const float* __restrict__ sp, size_t n)
{
    size_t i = (size_t)blockIdx.x*256 + threadIdx.x;
    if (i < n) f[i] += sp[(i / ((size_t)Sv*Dv)) * Dv + (i % Dv)];
}

// ---------- host ----------
static inline void tcg(const float* A, const float* Bt, float* C, const float* R,
                       int M, int N, int K, int acc, int gelu)
{
    mmagemm_kernel<<<dim3(N/128, M/128), 256, MM_SMEM>>>(A, Bt, C, R, N, K, acc, gelu);
}
static inline void wtrans(const float* W, float* T, int K, int N)
{
    wtrans_kernel<<<dim3(N/32, K/32), dim3(32, 8)>>>(W, T, K, N);
}
#define GS(p, s) cudaGetSymbolAddress((void**)&p, s)

extern "C" void kernel_launch(void* const* d_in, const int* in_sizes, int n_in,
                              void* d_out, int out_size)
{
    const float* x      = (const float*)d_in[0];
    const float* gm     = (const float*)d_in[1];
    const float* cs     = (const float*)d_in[2];
    const float* g1     = (const float*)d_in[3];
    const float* g2     = (const float*)d_in[4];
    const float* g3     = (const float*)d_in[5];
    const float* g4     = (const float*)d_in[6];
    const float* w_qkv  = (const float*)d_in[7];
    const float* w_lo   = (const float*)d_in[8];
    const float* w_gq   = (const float*)d_in[9];
    const float* w_gk   = (const float*)d_in[10];
    const float* w_gv   = (const float*)d_in[11];
    const float* w_go   = (const float*)d_in[12];
    const float* w_gate = (const float*)d_in[13];
    const float* w_mq   = (const float*)d_in[14];
    const float* w_mk   = (const float*)d_in[15];
    const float* w_mv   = (const float*)d_in[16];
    const float* w_mo   = (const float*)d_in[17];
    const float* w_cz   = (const float*)d_in[18];
    const float* w_cg   = (const float*)d_in[19];
    const float* w_sp   = (const float*)d_in[20];
    const float* w_fuse = (const float*)d_in[21];
    const float* w_ff1  = (const float*)d_in[22];
    const float* w_ff2  = (const float*)d_in[23];

    float* out      = (float*)d_out;
    float* outMem   = out + BSDv;
    float* outState = outMem + BMDv;

    float *h1,*qkv,*o_,*lcp,*h2,*qg,*kg,*vg,*readb,*gatelin,*go,*gmg;
    float *qm,*km,*vm,*wr,*pooled,*zlin,*gclin,*ns,*sp,*spf;
    float *fused,*hbuf,*h4,*ffa,*wa;
    GS(h1,d_h1); GS(qkv,d_qkv); GS(o_,d_o); GS(lcp,d_lcp); GS(h2,d_h2);
    GS(qg,d_qg); GS(kg,d_kg); GS(vg,d_vg); GS(readb,d_read); GS(gatelin,d_gatelin);
    GS(go,d_go); GS(gmg,d_gmg); GS(qm,d_qm); GS(km,d_km); GS(vm,d_vm);
    GS(wr,d_wr); GS(pooled,d_pooled); GS(zlin,d_zlin); GS(gclin,d_gclin);
    GS(ns,d_ns); GS(sp,d_sp); GS(spf,d_spf); GS(fused,d_fused); GS(hbuf,d_hbuf);
    GS(h4,d_h4); GS(ffa,d_ffa); GS(wa, warena);

    cudaFuncSetAttribute(attn_kernel, cudaFuncAttributeMaxDynamicSharedMemorySize, ATTN_SMEM);
    cudaFuncSetAttribute(mmagemm_kernel, cudaFuncAttributeMaxDynamicSharedMemorySize, MM_SMEM);

    const float scale = 0.08838834764831845f;
    int eb = (int)((BSDv + 255) / 256);

    // prologue ordered so ncu launch ~#6 hits a GEMM or attention
    wtrans(w_qkv, wa+OFF_QKV, Dv, 3*Dv);                        // 1
    wtrans(w_lo,  wa+OFF_LO,  Dv, Dv);                          // 2
    rmsnorm_kernel<<<BSv, 256>>>(x, g1, h1, 0);                 // 3
    tcg(h1, wa+OFF_QKV, qkv, nullptr, BSv, 3*Dv, Dv, 0, 0);     // 4
    // 5: local windowed attention
    {
        long long qsB = (long long)Sv*3*Dv, qsG = (long long)WINv*3*Dv, qsR = 3*Dv;
        long long osB = (long long)Sv*Dv, osG = (long long)WINv*Dv, osR = Dv;
        attn_kernel<<<Bv*nWv*Hv*(WINv/64), 64, ATTN_SMEM>>>(
            qkv, qkv+Dv, qkv+2*Dv, o_, nWv, WINv, WINv,
            qsB, qsG, qsR, qsB, qsG, qsR, osB, osG, osR, scale);
    }
    tcg(o_, wa+OFF_LO, lcp, x, BSv, Dv, Dv, 0, 0);              // 6: lcp = x + o@w_lo

    // remaining weight transposes
    wtrans(w_gq,   wa+OFF_GQ,   Dv, Dv);
    wtrans(w_gk,   wa+OFF_GK,   Dv, Dv);
    wtrans(w_gv,   wa+OFF_GV,   Dv, Dv);
    wtrans(w_go,   wa+OFF_GO,   Dv, Dv);
    wtrans(w_gate, wa+OFF_GATE, Dv, Dv);
    wtrans(w_mq,   wa+OFF_MQ,   Dv, Dv);
    wtrans(w_mk,   wa+OFF_MK,   Dv, Dv);
    wtrans(w_mv,   wa+OFF_MV,   Dv, Dv);
    wtrans(w_mo,   wa+OFF_MO,   Dv, Dv);
    wtrans(w_fuse,      wa+OFF_F1, Dv, Dv);
    wtrans(w_fuse + D2, wa+OFF_F2, Dv, Dv);
    wtrans(w_ff1,  wa+OFF_FF1,  Dv, FFv);
    wtrans(w_ff2,  wa+OFF_FF2,  FFv, Dv);

    // h2 = rmsnorm(lcp,g2); projections straight from fp32 h2
    rmsnorm_kernel<<<BSv, 256>>>(lcp, g2, h2, 0);
    tcg(h2, wa+OFF_GQ,   qg,      nullptr, BSv, Dv, Dv, 0, 0);
    tcg(h2, wa+OFF_GATE, gatelin, nullptr, BSv, Dv, Dv, 0, 0);
    tcg(h2, wa+OFF_MK,   km,      nullptr, BSv, Dv, Dv, 0, 0);
    tcg(h2, wa+OFF_MV,   vm,      nullptr, BSv, Dv, Dv, 0, 0);

    // gm-based projections (M=256) — gm used directly, no conversion
    tcg(gm, wa+OFF_GK, kg, nullptr, Bv*Mv, Dv, Dv, 0, 0);
    tcg(gm, wa+OFF_GV, vg, nullptr, Bv*Mv, Dv, Dv, 0, 0);
    tcg(gm, wa+OFF_MQ, qm, nullptr, Bv*Mv, Dv, Dv, 0, 0);

    // global read attention (Lq=S, Lk=M)
    {
        long long qsB = (long long)Sv*Dv, ksB = (long long)Mv*Dv;
        attn_kernel<<<Bv*Hv*(Sv/64), 64, ATTN_SMEM>>>(
            qg, kg, vg, readb, 1, Sv, Mv,
            qsB, 0, Dv, ksB, 0, Dv, qsB, 0, Dv, scale);
    }

    // gmg = h2 + sigmoid(gatelin) * (read@w_go)
    tcg(readb, wa+OFF_GO, go, nullptr, BSv, Dv, Dv, 0, 0);
    gmg_combine_kernel<<<eb, 256>>>(h2, gatelin, go, gmg, BSDv);

    // memory write attention (Lq=M, Lk=S)
    {
        long long qsB = (long long)Mv*Dv, ksB = (long long)Sv*Dv;
        attn_kernel<<<Bv*Hv*(Mv/64), 64, ATTN_SMEM>>>(
            qm, km, vm, wr, 1, Mv, Sv,
            qsB, 0, Dv, ksB, 0, Dv, qsB, 0, Dv, scale);
    }

    // new_memory = gm + wr@w_mo (fused residual, direct to d_out)
    tcg(wr, wa+OFF_MO, outMem, gm, Bv*Mv, Dv, Dv, 0, 0);

    // pooled / state / sp / spf
    meanpool_kernel<<<(BDv+255)/256, 256>>>(gmg, pooled);
    small_gemm_kernel<<<(Bv*Cv+255)/256, 256>>>(pooled, w_cz, zlin, Bv, Cv, Dv);
    small_gemm_kernel<<<(Bv*Cv+255)/256, 256>>>(pooled, w_cg, gclin, Bv, Cv, Dv);
    state_kernel<<<(BCv+255)/256, 256>>>(zlin, gclin, cs, ns, outState);
    small_gemm_kernel<<<(Bv*Dv+255)/256, 256>>>(ns, w_sp, sp, Bv, Dv, Cv);
    small_gemm_kernel<<<(Bv*Dv+255)/256, 256>>>(sp, w_fuse + 2*D2, spf, Bv, Dv, Dv);

    // fused = lcp@F1 + gmg@F2 + bcast(spf)
    tcg(lcp, wa+OFF_F1, fused, nullptr, BSv, Dv, Dv, 0, 0);
    tcg(gmg, wa+OFF_F2, fused, nullptr, BSv, Dv, Dv, 1, 0);
    bcast_add_kernel<<<eb, 256>>>(fused, spf, BSDv);

    // h = fused + rmsnorm(fused,g3); h4 = rmsnorm(h,g4)
    rmsnorm_kernel<<<BSv, 256>>>(fused, g3, hbuf, 1);
    rmsnorm_kernel<<<BSv, 256>>>(hbuf, g4, h4, 0);

    // FFN: ffa = gelu(h4@FF1) fused in epilogue; out = hbuf + ffa@FF2
    tcg(h4, wa+OFF_FF1, ffa, nullptr, BSv, FFv, Dv, 0, 1);
    tcg(ffa, wa+OFF_FF2, out, hbuf, BSv, Dv, FFv, 0, 0);
}